// round 15
// baseline (speedup 1.0000x reference)
#include <cuda_runtime.h>
#include <cuda_bf16.h>
#include <cstdint>

#define NN 40000
#define EE 640000
#define DIN 256
#define HH 128
#define CC 64

// ---------------------------------------------------------------------------
// Scratch (device globals)
// ---------------------------------------------------------------------------
__device__ float g_y[NN * HH];
__device__ float g_h[NN * HH];
__device__ __nv_bfloat16 g_acat[(NN + 128) * 2 * HH];   // h [hi|lo]
__device__ __nv_bfloat16 g_w1c[HH * 2 * DIN];
__device__ __nv_bfloat16 g_wmc[2 * HH * 2 * HH];
__device__ __nv_bfloat16 g_w2c[CC * 2 * HH];
__device__ int  g_cnt[NN];
__device__ int  g_rowptr[NN + 1];
__device__ int  g_cursor[NN];
__device__ int2 g_cpack[EE];

// Side stream + events (static init, before any capture)
static cudaStream_t g_side = nullptr;
static cudaEvent_t  g_ev0 = nullptr, g_ev1 = nullptr;
static struct _SideInit {
    _SideInit() {
        if (cudaStreamCreateWithFlags(&g_side, cudaStreamNonBlocking) != cudaSuccess) g_side = nullptr;
        if (cudaEventCreateWithFlags(&g_ev0, cudaEventDisableTiming) != cudaSuccess) g_ev0 = nullptr;
        if (cudaEventCreateWithFlags(&g_ev1, cudaEventDisableTiming) != cudaSuccess) g_ev1 = nullptr;
    }
} _side_init;

__device__ __forceinline__ uint32_t smem_u32(const void* p) {
    uint32_t a;
    asm("{ .reg .u64 t; cvta.to.shared.u64 t, %1; cvt.u32.u64 %0, t; }" : "=r"(a) : "l"(p));
    return a;
}
__device__ __forceinline__ void cp16(uint32_t dst, const void* src) {
    asm volatile("cp.async.cg.shared.global [%0], [%1], 16;" :: "r"(dst), "l"(src));
}
#define CP_COMMIT() asm volatile("cp.async.commit_group;" ::: "memory")
#define CP_WAIT1()  asm volatile("cp.async.wait_group 1;" ::: "memory")
#define CP_WAIT0()  asm volatile("cp.async.wait_group 0;" ::: "memory")

__device__ __forceinline__ __nv_bfloat162 bhi2(float x, float y) {
    __nv_bfloat162 p;
    p.x = __float2bfloat16(x);
    p.y = __float2bfloat16(y);
    return p;
}
__device__ __forceinline__ __nv_bfloat162 blo2(float x, float y, __nv_bfloat162 h) {
    __nv_bfloat162 p;
    p.x = __float2bfloat16(x - __bfloat162float(h.x));
    p.y = __float2bfloat16(y - __bfloat162float(h.y));
    return p;
}

#define MMA3(accv, ahv, alv, bhv, blv)                                          \
    asm volatile("mma.sync.aligned.m16n8k16.row.col.f32.bf16.bf16.f32 "         \
        "{%0,%1,%2,%3}, {%4,%5,%6,%7}, {%8,%9}, {%0,%1,%2,%3};"                 \
        : "+f"((accv)[0]), "+f"((accv)[1]), "+f"((accv)[2]), "+f"((accv)[3])    \
        : "r"((ahv)[0]), "r"((ahv)[1]), "r"((ahv)[2]), "r"((ahv)[3]),           \
          "r"((bhv)[0]), "r"((bhv)[1]));                                        \
    asm volatile("mma.sync.aligned.m16n8k16.row.col.f32.bf16.bf16.f32 "         \
        "{%0,%1,%2,%3}, {%4,%5,%6,%7}, {%8,%9}, {%0,%1,%2,%3};"                 \
        : "+f"((accv)[0]), "+f"((accv)[1]), "+f"((accv)[2]), "+f"((accv)[3])    \
        : "r"((alv)[0]), "r"((alv)[1]), "r"((alv)[2]), "r"((alv)[3]),           \
          "r"((bhv)[0]), "r"((bhv)[1]));                                        \
    asm volatile("mma.sync.aligned.m16n8k16.row.col.f32.bf16.bf16.f32 "         \
        "{%0,%1,%2,%3}, {%4,%5,%6,%7}, {%8,%9}, {%0,%1,%2,%3};"                 \
        : "+f"((accv)[0]), "+f"((accv)[1]), "+f"((accv)[2]), "+f"((accv)[3])    \
        : "r"((ahv)[0]), "r"((ahv)[1]), "r"((ahv)[2]), "r"((ahv)[3]),           \
          "r"((blv)[0]), "r"((blv)[1]));

// ---------------------------------------------------------------------------
// GEMM variant 1 (stage 1): fp32 x [M,256] converted in-kernel to [hi|lo].
// (Byte-identical to the R8 kernel measured at 203.7us.)
// ---------------------------------------------------------------------------
__global__ __launch_bounds__(256)
void gemm_mma_x(const float* __restrict__ X,
                const __nv_bfloat16* __restrict__ BT2,
                const float* __restrict__ bias,
                float* __restrict__ Out, int M) {
    constexpr int N_ = 128, K = 256;
    constexpr int NF = N_ / 16;
    constexpr int NITER = K / 64;
    constexpr int BROW = 4 * K;
    constexpr int ABUF = 128 * 128;

    extern __shared__ uint8_t smem[];
    uint8_t* sB = smem;
    uint8_t* sAhi = smem + N_ * BROW;
    uint8_t* sAlo = sAhi + ABUF;
    const uint32_t sBu = smem_u32(sB);
    const uint32_t sHu = smem_u32(sAhi);
    const uint32_t sLu = smem_u32(sAlo);

    const int tid = threadIdx.x;
    const int wid = tid >> 5;
    const int lane = tid & 31;
    const int wm = wid >> 1;
    const int wn = wid & 1;
    const int m0 = blockIdx.x * 128;

    float acc[2][NF][4];
    #pragma unroll
    for (int i = 0; i < 2; i++)
        #pragma unroll
        for (int j = 0; j < NF; j++)
            #pragma unroll
            for (int q = 0; q < 4; q++) acc[i][j][q] = 0.f;

    for (int idx = tid; idx < N_ * (2 * K) / 8; idx += 256) {
        int r = idx / ((2 * K) / 8);
        int kz = (idx % ((2 * K) / 8)) * 8;
        uint32_t dst = sBu + r * BROW + ((kz >> 6) << 7) + ((((kz >> 3) & 7) ^ (r & 7)) << 4);
        cp16(dst, BT2 + (size_t)r * 2 * K + kz);
    }
    CP_COMMIT();
    CP_WAIT0();

    for (int it = 0; it < NITER; it++) {
        __syncthreads();
        #pragma unroll
        for (int s = 0; s < 8; s++) {
            int idx = s * 256 + tid;
            int r = idx >> 4;
            int c4 = idx & 15;
            int k = c4 * 4;
            float4 v = make_float4(0.f, 0.f, 0.f, 0.f);
            if (m0 + r < M)
                v = __ldg((const float4*)(X + (size_t)(m0 + r) * K + it * 64) + c4);
            __nv_bfloat162 h[2], l[2];
            h[0] = bhi2(v.x, v.y); h[1] = bhi2(v.z, v.w);
            l[0] = blo2(v.x, v.y, h[0]); l[1] = blo2(v.z, v.w, h[1]);
            uint32_t off = r * 128 + (((k >> 3) ^ (r & 7)) << 4) + ((k & 4) << 1);
            *(uint2*)(sAhi + off) = *(const uint2*)h;
            *(uint2*)(sAlo + off) = *(const uint2*)l;
        }
        __syncthreads();

        #pragma unroll
        for (int ks = 0; ks < 4; ks++) {
            const int kk = ks * 16;
            uint32_t ah[2][4], al[2][4];
            #pragma unroll
            for (int mf = 0; mf < 2; mf++) {
                int r = wm * 32 + mf * 16 + (lane & 15);
                int kz = kk + (lane >> 4) * 8;
                uint32_t off = r * 128 + ((((kz >> 3) ^ (r & 7)) & 7) << 4);
                asm volatile("ldmatrix.sync.aligned.m8n8.x4.shared.b16 {%0,%1,%2,%3}, [%4];"
                    : "=r"(ah[mf][0]), "=r"(ah[mf][1]), "=r"(ah[mf][2]), "=r"(ah[mf][3])
                    : "r"(sHu + off));
                asm volatile("ldmatrix.sync.aligned.m8n8.x4.shared.b16 {%0,%1,%2,%3}, [%4];"
                    : "=r"(al[mf][0]), "=r"(al[mf][1]), "=r"(al[mf][2]), "=r"(al[mf][3])
                    : "r"(sLu + off));
            }
            uint32_t bh[NF][2], bl[NF][2];
            #pragma unroll
            for (int nf2 = 0; nf2 < NF / 2; nf2++) {
                int r = wn * (NF * 8) + nf2 * 16 + (lane & 7) + ((lane >> 4) << 3);
                int kzh = it * 64 + kk + ((lane >> 3) & 1) * 8;
                int kzl = kzh + K;
                uint32_t adh = sBu + r * BROW + ((kzh >> 6) << 7) + ((((kzh >> 3) & 7) ^ (r & 7)) << 4);
                uint32_t adl = sBu + r * BROW + ((kzl >> 6) << 7) + ((((kzl >> 3) & 7) ^ (r & 7)) << 4);
                asm volatile("ldmatrix.sync.aligned.m8n8.x4.shared.b16 {%0,%1,%2,%3}, [%4];"
                    : "=r"(bh[2 * nf2][0]), "=r"(bh[2 * nf2][1]),
                      "=r"(bh[2 * nf2 + 1][0]), "=r"(bh[2 * nf2 + 1][1]) : "r"(adh));
                asm volatile("ldmatrix.sync.aligned.m8n8.x4.shared.b16 {%0,%1,%2,%3}, [%4];"
                    : "=r"(bl[2 * nf2][0]), "=r"(bl[2 * nf2][1]),
                      "=r"(bl[2 * nf2 + 1][0]), "=r"(bl[2 * nf2 + 1][1]) : "r"(adl));
            }
            #pragma unroll
            for (int mf = 0; mf < 2; mf++)
                #pragma unroll
                for (int nf = 0; nf < NF; nf++) {
                    MMA3(acc[mf][nf], ah[mf], al[mf], bh[nf], bl[nf]);
                }
        }
    }

    #pragma unroll
    for (int mf = 0; mf < 2; mf++) {
        int r1 = m0 + wm * 32 + mf * 16 + (lane >> 2);
        int r2 = r1 + 8;
        #pragma unroll
        for (int nf = 0; nf < NF; nf++) {
            int col = wn * (NF * 8) + nf * 8 + (lane & 3) * 2;
            float bx = __ldg(bias + col), by = __ldg(bias + col + 1);
            if (r1 < M) {
                float2 v = make_float2(acc[mf][nf][0] + bx, acc[mf][nf][1] + by);
                *(float2*)(Out + (size_t)r1 * 128 + col) = v;
            }
            if (r2 < M) {
                float2 v = make_float2(acc[mf][nf][2] + bx, acc[mf][nf][3] + by);
                *(float2*)(Out + (size_t)r2 * 128 + col) = v;
            }
        }
    }
}

// ---------------------------------------------------------------------------
// GEMM (stages 2-4): A2 [M,2K]=[hi|lo] bf16 cp.async double-buffered;
// B resident. (Byte-identical to the R8 kernel measured at 203.7us.)
// ---------------------------------------------------------------------------
template<int N_, int K>
__global__ __launch_bounds__(256)
void gemm_mma(const __nv_bfloat16* __restrict__ A2,
              const __nv_bfloat16* __restrict__ BT2,
              const float* __restrict__ bias,
              float* __restrict__ Out, int M) {
    constexpr int NF = N_ / 16;
    constexpr int NITER = K / 64;
    constexpr int BROW = 4 * K;
    constexpr int ABUF = 128 * 128;

    extern __shared__ uint8_t smem[];
    uint8_t* sB = smem;
    uint8_t* sA = smem + N_ * BROW;
    const uint32_t sBu = smem_u32(sB);
    const uint32_t sAu = smem_u32(sA);

    const int tid = threadIdx.x;
    const int wid = tid >> 5;
    const int lane = tid & 31;
    const int wm = wid >> 1;
    const int wn = wid & 1;
    const int m0 = blockIdx.x * 128;

    float acc[2][NF][4];
    #pragma unroll
    for (int i = 0; i < 2; i++)
        #pragma unroll
        for (int j = 0; j < NF; j++)
            #pragma unroll
            for (int q = 0; q < 4; q++) acc[i][j][q] = 0.f;

    for (int idx = tid; idx < N_ * (2 * K) / 8; idx += 256) {
        int r = idx / ((2 * K) / 8);
        int kz = (idx % ((2 * K) / 8)) * 8;
        uint32_t dst = sBu + r * BROW + ((kz >> 6) << 7) + ((((kz >> 3) & 7) ^ (r & 7)) << 4);
        cp16(dst, BT2 + (size_t)r * 2 * K + kz);
    }
    auto stageA = [&](int it, int buf) {
        #pragma unroll
        for (int s = 0; s < 8; s++) {
            int idx = s * 256 + tid;
            int hilo = idx >> 10;
            int rem = idx & 1023;
            int r = rem >> 3, c = rem & 7;
            uint32_t dst = sAu + (uint32_t)(buf * 2 + hilo) * ABUF + r * 128 + ((c ^ (r & 7)) << 4);
            cp16(dst, A2 + (size_t)(m0 + r) * 2 * K + hilo * K + it * 64 + c * 8);
        }
    };
    stageA(0, 0);
    CP_COMMIT();

    for (int it = 0; it < NITER; it++) {
        const int buf = it & 1;
        if (it + 1 < NITER) stageA(it + 1, buf ^ 1);
        CP_COMMIT();
        CP_WAIT1();
        __syncthreads();

        const uint32_t aHi = sAu + (uint32_t)(buf * 2) * ABUF;
        const uint32_t aLo = aHi + ABUF;
        #pragma unroll
        for (int ks = 0; ks < 4; ks++) {
            const int kk = ks * 16;
            uint32_t ah[2][4], al[2][4];
            #pragma unroll
            for (int mf = 0; mf < 2; mf++) {
                int r = wm * 32 + mf * 16 + (lane & 15);
                int kz = kk + (lane >> 4) * 8;
                uint32_t off = r * 128 + ((((kz >> 3) ^ (r & 7)) & 7) << 4);
                asm volatile("ldmatrix.sync.aligned.m8n8.x4.shared.b16 {%0,%1,%2,%3}, [%4];"
                    : "=r"(ah[mf][0]), "=r"(ah[mf][1]), "=r"(ah[mf][2]), "=r"(ah[mf][3])
                    : "r"(aHi + off));
                asm volatile("ldmatrix.sync.aligned.m8n8.x4.shared.b16 {%0,%1,%2,%3}, [%4];"
                    : "=r"(al[mf][0]), "=r"(al[mf][1]), "=r"(al[mf][2]), "=r"(al[mf][3])
                    : "r"(aLo + off));
            }
            uint32_t bh[NF][2], bl[NF][2];
            #pragma unroll
            for (int nf2 = 0; nf2 < NF / 2; nf2++) {
                int r = wn * (NF * 8) + nf2 * 16 + (lane & 7) + ((lane >> 4) << 3);
                int kzh = it * 64 + kk + ((lane >> 3) & 1) * 8;
                int kzl = kzh + K;
                uint32_t adh = sBu + r * BROW + ((kzh >> 6) << 7) + ((((kzh >> 3) & 7) ^ (r & 7)) << 4);
                uint32_t adl = sBu + r * BROW + ((kzl >> 6) << 7) + ((((kzl >> 3) & 7) ^ (r & 7)) << 4);
                asm volatile("ldmatrix.sync.aligned.m8n8.x4.shared.b16 {%0,%1,%2,%3}, [%4];"
                    : "=r"(bh[2 * nf2][0]), "=r"(bh[2 * nf2][1]),
                      "=r"(bh[2 * nf2 + 1][0]), "=r"(bh[2 * nf2 + 1][1]) : "r"(adh));
                asm volatile("ldmatrix.sync.aligned.m8n8.x4.shared.b16 {%0,%1,%2,%3}, [%4];"
                    : "=r"(bl[2 * nf2][0]), "=r"(bl[2 * nf2][1]),
                      "=r"(bl[2 * nf2 + 1][0]), "=r"(bl[2 * nf2 + 1][1]) : "r"(adl));
            }
            #pragma unroll
            for (int mf = 0; mf < 2; mf++)
                #pragma unroll
                for (int nf = 0; nf < NF; nf++) {
                    MMA3(acc[mf][nf], ah[mf], al[mf], bh[nf], bl[nf]);
                }
        }
        __syncthreads();
    }

    #pragma unroll
    for (int mf = 0; mf < 2; mf++) {
        int r1 = m0 + wm * 32 + mf * 16 + (lane >> 2);
        int r2 = r1 + 8;
        #pragma unroll
        for (int nf = 0; nf < NF; nf++) {
            int col = wn * (NF * 8) + nf * 8 + (lane & 3) * 2;
            float bx = __ldg(bias + col), by = __ldg(bias + col + 1);
            if (r1 < M) {
                float2 v = make_float2(acc[mf][nf][0] + bx, acc[mf][nf][1] + by);
                *(float2*)(Out + (size_t)r1 * N_ + col) = v;
            }
            if (r2 < M) {
                float2 v = make_float2(acc[mf][nf][2] + bx, acc[mf][nf][3] + by);
                *(float2*)(Out + (size_t)r2 * N_ + col) = v;
            }
        }
    }
}

// ---------------------------------------------------------------------------
// Weight prep, split: w1 on critical path, wm/w2 on side stream.
// ---------------------------------------------------------------------------
__global__ void prep_w1(const float* __restrict__ w1, __nv_bfloat16* __restrict__ w1c) {
    int j = blockIdx.x * blockDim.x + threadIdx.x;
    if (j >= DIN * HH) return;
    int k = j / HH, n = j % HH;
    float f = w1[j];
    __nv_bfloat16 h = __float2bfloat16(f);
    __nv_bfloat16* dhi = w1c + (size_t)n * 2 * DIN + k;
    dhi[0] = h;
    dhi[DIN] = __float2bfloat16(f - __bfloat162float(h));
}
__global__ void prep_wrest(const float* __restrict__ wm, const float* __restrict__ w2,
                           __nv_bfloat16* __restrict__ wmc, __nv_bfloat16* __restrict__ w2c) {
    int j = blockIdx.x * blockDim.x + threadIdx.x;
    float f;
    __nv_bfloat16* dhi;
    if (j < 2 * HH * HH) {
        int l = j >> 14;
        int q = j & 16383;
        int k = q / HH, n = q % HH;
        f = wm[j];
        dhi = wmc + (size_t)l * HH * 2 * HH + (size_t)n * 2 * HH + k;
    } else if (j < 2 * HH * HH + HH * CC) {
        int q = j - 2 * HH * HH;
        int k = q / CC, n = q % CC;
        f = w2[q];
        dhi = w2c + (size_t)n * 2 * HH + k;
    } else return;
    __nv_bfloat16 h = __float2bfloat16(f);
    dhi[0] = h;
    dhi[HH] = __float2bfloat16(f - __bfloat162float(h));
}

// ---------------------------------------------------------------------------
// CSR construction
// ---------------------------------------------------------------------------
__global__ void hist_kernel(const int* __restrict__ row, int* __restrict__ cnt, int E) {
    int i = blockIdx.x * blockDim.x + threadIdx.x;
    if (i < E) atomicAdd(&cnt[row[i]], 1);
}
__global__ void scan_kernel(int* __restrict__ cnt, int* __restrict__ rowptr,
                            int* __restrict__ cursor) {
    __shared__ int wsum[32];
    __shared__ int carry_s;
    const int tid = threadIdx.x;
    const int lane = tid & 31;
    const int wid = tid >> 5;
    if (tid == 0) { carry_s = 0; rowptr[0] = 0; }
    __syncthreads();
    for (int base = 0; base < NN; base += 1024) {
        int i = base + tid;
        int v = (i < NN) ? cnt[i] : 0;
        if (i < NN) cnt[i] = 0;
        int incl = v;
        #pragma unroll
        for (int o = 1; o < 32; o <<= 1) {
            int t = __shfl_up_sync(0xFFFFFFFFu, incl, o);
            if (lane >= o) incl += t;
        }
        if (lane == 31) wsum[wid] = incl;
        __syncthreads();
        if (wid == 0) {
            int w = wsum[lane];
            #pragma unroll
            for (int o = 1; o < 32; o <<= 1) {
                int t = __shfl_up_sync(0xFFFFFFFFu, w, o);
                if (lane >= o) w += t;
            }
            wsum[lane] = w;
        }
        __syncthreads();
        int offset = (wid > 0) ? wsum[wid - 1] : 0;
        int total = wsum[31];
        int carry = carry_s;
        incl += offset;
        if (i < NN) {
            rowptr[i + 1] = carry + incl;
            cursor[i]     = carry + incl - v;
        }
        __syncthreads();
        if (tid == 0) carry_s = carry + total;
        __syncthreads();
    }
}
__global__ void scatter_kernel(const int* __restrict__ row, const int* __restrict__ col,
                               const float* __restrict__ val, int* __restrict__ cursor,
                               int2* __restrict__ cpack, int E) {
    int i = blockIdx.x * blockDim.x + threadIdx.x;
    if (i >= E) return;
    int pos = atomicAdd(&cursor[row[i]], 1);
    cpack[pos] = make_int2(col[i], __float_as_int(val[i]));
}

// ---------------------------------------------------------------------------
// CSR SPMM: one warp per row, 4-deep gather pipeline, fused epilogue + bf16
// [hi|lo] split. (Byte-identical to the R8 kernel measured at 203.7us.)
// ---------------------------------------------------------------------------
template<int D, int MODE>
__global__ void spmm_csr(const int* __restrict__ rowptr, const int2* __restrict__ cpack,
                         const float* __restrict__ mat, float* __restrict__ dst,
                         const float* __restrict__ ts, __nv_bfloat16* __restrict__ acat) {
    int r = blockIdx.x * (blockDim.x >> 5) + (threadIdx.x >> 5);
    if (r >= NN) return;
    int lane = threadIdx.x & 31;
    int s = __ldg(&rowptr[r]);
    int e = __ldg(&rowptr[r + 1]);

    if (D == 128) {
        float4 acc = make_float4(0.f, 0.f, 0.f, 0.f);
        int i = s;
        for (; i + 4 <= e; i += 4) {
            int2 p0 = __ldg(&cpack[i]);
            int2 p1 = __ldg(&cpack[i + 1]);
            int2 p2 = __ldg(&cpack[i + 2]);
            int2 p3 = __ldg(&cpack[i + 3]);
            float4 m0 = __ldg((const float4*)(mat + (size_t)p0.x * 128) + lane);
            float4 m1 = __ldg((const float4*)(mat + (size_t)p1.x * 128) + lane);
            float4 m2 = __ldg((const float4*)(mat + (size_t)p2.x * 128) + lane);
            float4 m3 = __ldg((const float4*)(mat + (size_t)p3.x * 128) + lane);
            float v0 = __int_as_float(p0.y), v1 = __int_as_float(p1.y);
            float v2 = __int_as_float(p2.y), v3 = __int_as_float(p3.y);
            acc.x = fmaf(v0, m0.x, acc.x); acc.y = fmaf(v0, m0.y, acc.y);
            acc.z = fmaf(v0, m0.z, acc.z); acc.w = fmaf(v0, m0.w, acc.w);
            acc.x = fmaf(v1, m1.x, acc.x); acc.y = fmaf(v1, m1.y, acc.y);
            acc.z = fmaf(v1, m1.z, acc.z); acc.w = fmaf(v1, m1.w, acc.w);
            acc.x = fmaf(v2, m2.x, acc.x); acc.y = fmaf(v2, m2.y, acc.y);
            acc.z = fmaf(v2, m2.z, acc.z); acc.w = fmaf(v2, m2.w, acc.w);
            acc.x = fmaf(v3, m3.x, acc.x); acc.y = fmaf(v3, m3.y, acc.y);
            acc.z = fmaf(v3, m3.z, acc.z); acc.w = fmaf(v3, m3.w, acc.w);
        }
        for (; i < e; i++) {
            int2 p = __ldg(&cpack[i]);
            float v = __int_as_float(p.y);
            float4 m = __ldg((const float4*)(mat + (size_t)p.x * 128) + lane);
            acc.x = fmaf(v, m.x, acc.x); acc.y = fmaf(v, m.y, acc.y);
            acc.z = fmaf(v, m.z, acc.z); acc.w = fmaf(v, m.w, acc.w);
        }
        float4* o = (float4*)(dst + (size_t)r * 128) + lane;
        float4 hv;
        if (MODE == 0) {
            hv.x = fmaxf(acc.x, 0.f); hv.y = fmaxf(acc.y, 0.f);
            hv.z = fmaxf(acc.z, 0.f); hv.w = fmaxf(acc.w, 0.f);
        } else {
            float dt = *ts;
            hv = *o;
            hv.x = fmaf(fmaxf(acc.x, 0.f), dt, hv.x);
            hv.y = fmaf(fmaxf(acc.y, 0.f), dt, hv.y);
            hv.z = fmaf(fmaxf(acc.z, 0.f), dt, hv.z);
            hv.w = fmaf(fmaxf(acc.w, 0.f), dt, hv.w);
        }
        *o = hv;
        __nv_bfloat162 hl[2], ll[2];
        hl[0] = bhi2(hv.x, hv.y); hl[1] = bhi2(hv.z, hv.w);
        ll[0] = blo2(hv.x, hv.y, hl[0]); ll[1] = blo2(hv.z, hv.w, hl[1]);
        __nv_bfloat16* row = acat + (size_t)r * 256;
        *(uint2*)(row + lane * 4)       = *(const uint2*)hl;
        *(uint2*)(row + 128 + lane * 4) = *(const uint2*)ll;
    } else {
        float2 acc = make_float2(0.f, 0.f);
        int i = s;
        for (; i + 4 <= e; i += 4) {
            int2 p0 = __ldg(&cpack[i]);
            int2 p1 = __ldg(&cpack[i + 1]);
            int2 p2 = __ldg(&cpack[i + 2]);
            int2 p3 = __ldg(&cpack[i + 3]);
            float2 m0 = __ldg((const float2*)(mat + (size_t)p0.x * 64) + lane);
            float2 m1 = __ldg((const float2*)(mat + (size_t)p1.x * 64) + lane);
            float2 m2 = __ldg((const float2*)(mat + (size_t)p2.x * 64) + lane);
            float2 m3 = __ldg((const float2*)(mat + (size_t)p3.x * 64) + lane);
            acc.x = fmaf(__int_as_float(p0.y), m0.x, acc.x);
            acc.y = fmaf(__int_as_float(p0.y), m0.y, acc.y);
            acc.x = fmaf(__int_as_float(p1.y), m1.x, acc.x);
            acc.y = fmaf(__int_as_float(p1.y), m1.y, acc.y);
            acc.x = fmaf(__int_as_float(p2.y), m2.x, acc.x);
            acc.y = fmaf(__int_as_float(p2.y), m2.y, acc.y);
            acc.x = fmaf(__int_as_float(p3.y), m3.x, acc.x);
            acc.y = fmaf(__int_as_float(p3.y), m3.y, acc.y);
        }
        for (; i < e; i++) {
            int2 p = __ldg(&cpack[i]);
            float v = __int_as_float(p.y);
            float2 m = __ldg((const float2*)(mat + (size_t)p.x * 64) + lane);
            acc.x = fmaf(v, m.x, acc.x);
            acc.y = fmaf(v, m.y, acc.y);
        }
        *((float2*)(dst + (size_t)r * 64) + lane) = acc;
    }
}

// ---------------------------------------------------------------------------
// Launch sequence (R8 topology; only change: prep split w1/wrest)
// ---------------------------------------------------------------------------
extern "C" void kernel_launch(void* const* d_in, const int* in_sizes, int n_in,
                              void* d_out, int out_size) {
    const float* x    = (const float*)d_in[0];
    const int*   erow = (const int*)  d_in[1];
    const int*   ecol = (const int*)  d_in[2];
    const float* eval = (const float*)d_in[3];
    const float* w1   = (const float*)d_in[4];
    const float* b1   = (const float*)d_in[5];
    const float* wm   = (const float*)d_in[6];
    const float* bm   = (const float*)d_in[7];
    const float* w2   = (const float*)d_in[8];
    const float* b2   = (const float*)d_in[9];
    const float* ts   = (const float*)d_in[10];
    float* out = (float*)d_out;

    float *y, *h;
    int *cnt, *rowptr, *cursor;
    int2* cpack;
    __nv_bfloat16 *acat, *w1c, *wmc, *w2c;
    cudaGetSymbolAddress((void**)&y,      g_y);
    cudaGetSymbolAddress((void**)&h,      g_h);
    cudaGetSymbolAddress((void**)&cnt,    g_cnt);
    cudaGetSymbolAddress((void**)&rowptr, g_rowptr);
    cudaGetSymbolAddress((void**)&cursor, g_cursor);
    cudaGetSymbolAddress((void**)&cpack,  g_cpack);
    cudaGetSymbolAddress((void**)&acat,   g_acat);
    cudaGetSymbolAddress((void**)&w1c,    g_w1c);
    cudaGetSymbolAddress((void**)&wmc,    g_wmc);
    cudaGetSymbolAddress((void**)&w2c,    g_w2c);

    const int SMX = 128 * (4 * DIN) + 2 * 128 * 128;  // 163840
    const int SM2 = 128 * (4 * HH)  + 4 * 128 * 128;  // 131072
    const int SM4 = 64  * (4 * HH)  + 4 * 128 * 128;  // 98304
    cudaFuncSetAttribute((const void*)&gemm_mma_x,
                         cudaFuncAttributeMaxDynamicSharedMemorySize, SMX);
    cudaFuncSetAttribute((const void*)&gemm_mma<128, HH>,
                         cudaFuncAttributeMaxDynamicSharedMemorySize, SM2);
    cudaFuncSetAttribute((const void*)&gemm_mma<64, HH>,
                         cudaFuncAttributeMaxDynamicSharedMemorySize, SM4);
    cudaGetLastError();

    const int gemm_blocks = (NN + 127) / 128;   // 313
    const int spmm_blocks = (NN + 7) / 8;       // 5000
    const int e_blocks = (EE + 255) / 256;

    const bool fork = (g_side != nullptr) && (g_ev0 != nullptr) && (g_ev1 != nullptr);

    if (fork) {
        cudaEventRecord(g_ev0, 0);
        cudaStreamWaitEvent(g_side, g_ev0, 0);
        prep_wrest<<<(2 * HH * HH + HH * CC + 255) / 256, 256, 0, g_side>>>(wm, w2, wmc, w2c);
        hist_kernel<<<e_blocks, 256, 0, g_side>>>(erow, cnt, EE);
        scan_kernel<<<1, 1024, 0, g_side>>>(cnt, rowptr, cursor);
        scatter_kernel<<<e_blocks, 256, 0, g_side>>>(erow, ecol, eval, cursor, cpack, EE);
        cudaEventRecord(g_ev1, g_side);
    }

    // Main stream: w1 split only, then stage-1 GEMM (x converted in-kernel)
    prep_w1<<<(DIN * HH + 255) / 256, 256>>>(w1, w1c);
    gemm_mma_x<<<gemm_blocks, 256, SMX>>>(x, w1c, b1, y, NN);

    if (fork) {
        cudaStreamWaitEvent(0, g_ev1, 0);
    } else {
        prep_wrest<<<(2 * HH * HH + HH * CC + 255) / 256, 256>>>(wm, w2, wmc, w2c);
        hist_kernel<<<e_blocks, 256>>>(erow, cnt, EE);
        scan_kernel<<<1, 1024>>>(cnt, rowptr, cursor);
        scatter_kernel<<<e_blocks, 256>>>(erow, ecol, eval, cursor, cpack, EE);
    }

    // Stage 1: h = relu(A @ (x W1 + b1))
    spmm_csr<128, 0><<<spmm_blocks, 256>>>(rowptr, cpack, y, h, ts, acat);

    // Stage 2,3: h += relu(A @ (h Wm + bm)) * dt
    for (int i = 0; i < 2; i++) {
        gemm_mma<128, HH><<<gemm_blocks, 256, SM2>>>(
            acat, wmc + (size_t)i * HH * 2 * HH, bm + (size_t)i * HH, y, NN);
        spmm_csr<128, 1><<<spmm_blocks, 256>>>(rowptr, cpack, y, h, ts, acat);
    }

    // Stage 4: out = A @ (h W2 + b2)
    gemm_mma<64, HH><<<gemm_blocks, 256, SM4>>>(acat, w2c, b2, y, NN);
    spmm_csr<64, 2><<<spmm_blocks, 256>>>(rowptr, cpack, y, out, ts, nullptr);
}

// round 16
// speedup vs baseline: 1.1065x; 1.1065x over previous
#include <cuda_runtime.h>
#include <cuda_bf16.h>
#include <cstdint>

#define NN 40000
#define EE 640000
#define DIN 256
#define HH 128
#define CC 64

// ---------------------------------------------------------------------------
// Scratch (device globals)
// ---------------------------------------------------------------------------
__device__ float g_y[NN * HH];
__device__ float g_h[NN * HH];
__device__ __nv_bfloat16 g_acat[(NN + 128) * 2 * HH];   // h [hi|lo]
__device__ __nv_bfloat16 g_w1c[HH * 2 * DIN];
__device__ __nv_bfloat16 g_wmc[2 * HH * 2 * HH];
__device__ __nv_bfloat16 g_w2c[CC * 2 * HH];
__device__ int  g_cnt[NN];
__device__ int  g_rowptr[NN + 1];
__device__ int  g_cursor[NN];
__device__ int2 g_cpack[EE];

// Side stream + events (static init, before any capture)
static cudaStream_t g_side = nullptr;
static cudaEvent_t  g_ev0 = nullptr, g_ev1 = nullptr;
static struct _SideInit {
    _SideInit() {
        if (cudaStreamCreateWithFlags(&g_side, cudaStreamNonBlocking) != cudaSuccess) g_side = nullptr;
        if (cudaEventCreateWithFlags(&g_ev0, cudaEventDisableTiming) != cudaSuccess) g_ev0 = nullptr;
        if (cudaEventCreateWithFlags(&g_ev1, cudaEventDisableTiming) != cudaSuccess) g_ev1 = nullptr;
    }
} _side_init;

__device__ __forceinline__ uint32_t smem_u32(const void* p) {
    uint32_t a;
    asm("{ .reg .u64 t; cvta.to.shared.u64 t, %1; cvt.u32.u64 %0, t; }" : "=r"(a) : "l"(p));
    return a;
}
__device__ __forceinline__ void cp16(uint32_t dst, const void* src) {
    asm volatile("cp.async.cg.shared.global [%0], [%1], 16;" :: "r"(dst), "l"(src));
}
#define CP_COMMIT() asm volatile("cp.async.commit_group;" ::: "memory")
#define CP_WAIT1()  asm volatile("cp.async.wait_group 1;" ::: "memory")
#define CP_WAIT0()  asm volatile("cp.async.wait_group 0;" ::: "memory")

__device__ __forceinline__ __nv_bfloat162 bhi2(float x, float y) {
    __nv_bfloat162 p;
    p.x = __float2bfloat16(x);
    p.y = __float2bfloat16(y);
    return p;
}
__device__ __forceinline__ __nv_bfloat162 blo2(float x, float y, __nv_bfloat162 h) {
    __nv_bfloat162 p;
    p.x = __float2bfloat16(x - __bfloat162float(h.x));
    p.y = __float2bfloat16(y - __bfloat162float(h.y));
    return p;
}

#define MMA3(accv, ahv, alv, bhv, blv)                                          \
    asm volatile("mma.sync.aligned.m16n8k16.row.col.f32.bf16.bf16.f32 "         \
        "{%0,%1,%2,%3}, {%4,%5,%6,%7}, {%8,%9}, {%0,%1,%2,%3};"                 \
        : "+f"((accv)[0]), "+f"((accv)[1]), "+f"((accv)[2]), "+f"((accv)[3])    \
        : "r"((ahv)[0]), "r"((ahv)[1]), "r"((ahv)[2]), "r"((ahv)[3]),           \
          "r"((bhv)[0]), "r"((bhv)[1]));                                        \
    asm volatile("mma.sync.aligned.m16n8k16.row.col.f32.bf16.bf16.f32 "         \
        "{%0,%1,%2,%3}, {%4,%5,%6,%7}, {%8,%9}, {%0,%1,%2,%3};"                 \
        : "+f"((accv)[0]), "+f"((accv)[1]), "+f"((accv)[2]), "+f"((accv)[3])    \
        : "r"((alv)[0]), "r"((alv)[1]), "r"((alv)[2]), "r"((alv)[3]),           \
          "r"((bhv)[0]), "r"((bhv)[1]));                                        \
    asm volatile("mma.sync.aligned.m16n8k16.row.col.f32.bf16.bf16.f32 "         \
        "{%0,%1,%2,%3}, {%4,%5,%6,%7}, {%8,%9}, {%0,%1,%2,%3};"                 \
        : "+f"((accv)[0]), "+f"((accv)[1]), "+f"((accv)[2]), "+f"((accv)[3])    \
        : "r"((ahv)[0]), "r"((ahv)[1]), "r"((ahv)[2]), "r"((ahv)[3]),           \
          "r"((blv)[0]), "r"((blv)[1]));

// ---------------------------------------------------------------------------
// GEMM variant 1 (stage 1): fp32 x [M,256]; converts to [hi|lo] bf16
// tiles in-kernel during staging (single-buffered). B resident [hi|lo].
// ---------------------------------------------------------------------------
__global__ __launch_bounds__(256)
void gemm_mma_x(const float* __restrict__ X,
                const __nv_bfloat16* __restrict__ BT2,
                const float* __restrict__ bias,
                float* __restrict__ Out, int M) {
    constexpr int N_ = 128, K = 256;
    constexpr int NF = N_ / 16;
    constexpr int NITER = K / 64;
    constexpr int BROW = 4 * K;           // 1024 B
    constexpr int ABUF = 128 * 128;       // 16 KB per tile

    extern __shared__ uint8_t smem[];
    uint8_t* sB = smem;                           // 128 KB
    uint8_t* sAhi = smem + N_ * BROW;             // 16 KB
    uint8_t* sAlo = sAhi + ABUF;                  // 16 KB
    const uint32_t sBu = smem_u32(sB);
    const uint32_t sHu = smem_u32(sAhi);
    const uint32_t sLu = smem_u32(sAlo);

    const int tid = threadIdx.x;
    const int wid = tid >> 5;
    const int lane = tid & 31;
    const int wm = wid >> 1;
    const int wn = wid & 1;
    const int m0 = blockIdx.x * 128;

    float acc[2][NF][4];
    #pragma unroll
    for (int i = 0; i < 2; i++)
        #pragma unroll
        for (int j = 0; j < NF; j++)
            #pragma unroll
            for (int q = 0; q < 4; q++) acc[i][j][q] = 0.f;

    // Resident B [128 x 2K bf16]
    for (int idx = tid; idx < N_ * (2 * K) / 8; idx += 256) {
        int r = idx / ((2 * K) / 8);
        int kz = (idx % ((2 * K) / 8)) * 8;
        uint32_t dst = sBu + r * BROW + ((kz >> 6) << 7) + ((((kz >> 3) & 7) ^ (r & 7)) << 4);
        cp16(dst, BT2 + (size_t)r * 2 * K + kz);
    }
    CP_COMMIT();
    CP_WAIT0();

    for (int it = 0; it < NITER; it++) {
        __syncthreads();
        // Stage + convert: 128 rows x 64 fp32 -> hi/lo bf16 tiles
        #pragma unroll
        for (int s = 0; s < 8; s++) {
            int idx = s * 256 + tid;          // 0..2047
            int r = idx >> 4;                 // 16 float4 per row
            int c4 = idx & 15;
            int k = c4 * 4;                   // 0..60
            float4 v = make_float4(0.f, 0.f, 0.f, 0.f);
            if (m0 + r < M)
                v = __ldg((const float4*)(X + (size_t)(m0 + r) * K + it * 64) + c4);
            __nv_bfloat162 h[2], l[2];
            h[0] = bhi2(v.x, v.y); h[1] = bhi2(v.z, v.w);
            l[0] = blo2(v.x, v.y, h[0]); l[1] = blo2(v.z, v.w, h[1]);
            uint32_t off = r * 128 + (((k >> 3) ^ (r & 7)) << 4) + ((k & 4) << 1);
            *(uint2*)(sAhi + off) = *(const uint2*)h;
            *(uint2*)(sAlo + off) = *(const uint2*)l;
        }
        __syncthreads();

        #pragma unroll
        for (int ks = 0; ks < 4; ks++) {
            const int kk = ks * 16;
            uint32_t ah[2][4], al[2][4];
            #pragma unroll
            for (int mf = 0; mf < 2; mf++) {
                int r = wm * 32 + mf * 16 + (lane & 15);
                int kz = kk + (lane >> 4) * 8;
                uint32_t off = r * 128 + ((((kz >> 3) ^ (r & 7)) & 7) << 4);
                asm volatile("ldmatrix.sync.aligned.m8n8.x4.shared.b16 {%0,%1,%2,%3}, [%4];"
                    : "=r"(ah[mf][0]), "=r"(ah[mf][1]), "=r"(ah[mf][2]), "=r"(ah[mf][3])
                    : "r"(sHu + off));
                asm volatile("ldmatrix.sync.aligned.m8n8.x4.shared.b16 {%0,%1,%2,%3}, [%4];"
                    : "=r"(al[mf][0]), "=r"(al[mf][1]), "=r"(al[mf][2]), "=r"(al[mf][3])
                    : "r"(sLu + off));
            }
            uint32_t bh[NF][2], bl[NF][2];
            #pragma unroll
            for (int nf2 = 0; nf2 < NF / 2; nf2++) {
                int r = wn * (NF * 8) + nf2 * 16 + (lane & 7) + ((lane >> 4) << 3);
                int kzh = it * 64 + kk + ((lane >> 3) & 1) * 8;
                int kzl = kzh + K;
                uint32_t adh = sBu + r * BROW + ((kzh >> 6) << 7) + ((((kzh >> 3) & 7) ^ (r & 7)) << 4);
                uint32_t adl = sBu + r * BROW + ((kzl >> 6) << 7) + ((((kzl >> 3) & 7) ^ (r & 7)) << 4);
                asm volatile("ldmatrix.sync.aligned.m8n8.x4.shared.b16 {%0,%1,%2,%3}, [%4];"
                    : "=r"(bh[2 * nf2][0]), "=r"(bh[2 * nf2][1]),
                      "=r"(bh[2 * nf2 + 1][0]), "=r"(bh[2 * nf2 + 1][1]) : "r"(adh));
                asm volatile("ldmatrix.sync.aligned.m8n8.x4.shared.b16 {%0,%1,%2,%3}, [%4];"
                    : "=r"(bl[2 * nf2][0]), "=r"(bl[2 * nf2][1]),
                      "=r"(bl[2 * nf2 + 1][0]), "=r"(bl[2 * nf2 + 1][1]) : "r"(adl));
            }
            #pragma unroll
            for (int mf = 0; mf < 2; mf++)
                #pragma unroll
                for (int nf = 0; nf < NF; nf++) {
                    MMA3(acc[mf][nf], ah[mf], al[mf], bh[nf], bl[nf]);
                }
        }
    }

    #pragma unroll
    for (int mf = 0; mf < 2; mf++) {
        int r1 = m0 + wm * 32 + mf * 16 + (lane >> 2);
        int r2 = r1 + 8;
        #pragma unroll
        for (int nf = 0; nf < NF; nf++) {
            int col = wn * (NF * 8) + nf * 8 + (lane & 3) * 2;
            float bx = __ldg(bias + col), by = __ldg(bias + col + 1);
            if (r1 < M) {
                float2 v = make_float2(acc[mf][nf][0] + bx, acc[mf][nf][1] + by);
                *(float2*)(Out + (size_t)r1 * 128 + col) = v;
            }
            if (r2 < M) {
                float2 v = make_float2(acc[mf][nf][2] + bx, acc[mf][nf][3] + by);
                *(float2*)(Out + (size_t)r2 * 128 + col) = v;
            }
        }
    }
}

// ---------------------------------------------------------------------------
// GEMM (stages 2-4): A2 [M,2K]=[hi|lo] bf16, cp.async double-buffered;
// B resident.
// ---------------------------------------------------------------------------
template<int N_, int K>
__global__ __launch_bounds__(256)
void gemm_mma(const __nv_bfloat16* __restrict__ A2,
              const __nv_bfloat16* __restrict__ BT2,
              const float* __restrict__ bias,
              float* __restrict__ Out, int M) {
    constexpr int NF = N_ / 16;
    constexpr int NITER = K / 64;
    constexpr int BROW = 4 * K;
    constexpr int ABUF = 128 * 128;

    extern __shared__ uint8_t smem[];
    uint8_t* sB = smem;
    uint8_t* sA = smem + N_ * BROW;
    const uint32_t sBu = smem_u32(sB);
    const uint32_t sAu = smem_u32(sA);

    const int tid = threadIdx.x;
    const int wid = tid >> 5;
    const int lane = tid & 31;
    const int wm = wid >> 1;
    const int wn = wid & 1;
    const int m0 = blockIdx.x * 128;

    float acc[2][NF][4];
    #pragma unroll
    for (int i = 0; i < 2; i++)
        #pragma unroll
        for (int j = 0; j < NF; j++)
            #pragma unroll
            for (int q = 0; q < 4; q++) acc[i][j][q] = 0.f;

    for (int idx = tid; idx < N_ * (2 * K) / 8; idx += 256) {
        int r = idx / ((2 * K) / 8);
        int kz = (idx % ((2 * K) / 8)) * 8;
        uint32_t dst = sBu + r * BROW + ((kz >> 6) << 7) + ((((kz >> 3) & 7) ^ (r & 7)) << 4);
        cp16(dst, BT2 + (size_t)r * 2 * K + kz);
    }
    auto stageA = [&](int it, int buf) {
        #pragma unroll
        for (int s = 0; s < 8; s++) {
            int idx = s * 256 + tid;
            int hilo = idx >> 10;
            int rem = idx & 1023;
            int r = rem >> 3, c = rem & 7;
            uint32_t dst = sAu + (uint32_t)(buf * 2 + hilo) * ABUF + r * 128 + ((c ^ (r & 7)) << 4);
            cp16(dst, A2 + (size_t)(m0 + r) * 2 * K + hilo * K + it * 64 + c * 8);
        }
    };
    stageA(0, 0);
    CP_COMMIT();

    for (int it = 0; it < NITER; it++) {
        const int buf = it & 1;
        if (it + 1 < NITER) stageA(it + 1, buf ^ 1);
        CP_COMMIT();
        CP_WAIT1();
        __syncthreads();

        const uint32_t aHi = sAu + (uint32_t)(buf * 2) * ABUF;
        const uint32_t aLo = aHi + ABUF;
        #pragma unroll
        for (int ks = 0; ks < 4; ks++) {
            const int kk = ks * 16;
            uint32_t ah[2][4], al[2][4];
            #pragma unroll
            for (int mf = 0; mf < 2; mf++) {
                int r = wm * 32 + mf * 16 + (lane & 15);
                int kz = kk + (lane >> 4) * 8;
                uint32_t off = r * 128 + ((((kz >> 3) ^ (r & 7)) & 7) << 4);
                asm volatile("ldmatrix.sync.aligned.m8n8.x4.shared.b16 {%0,%1,%2,%3}, [%4];"
                    : "=r"(ah[mf][0]), "=r"(ah[mf][1]), "=r"(ah[mf][2]), "=r"(ah[mf][3])
                    : "r"(aHi + off));
                asm volatile("ldmatrix.sync.aligned.m8n8.x4.shared.b16 {%0,%1,%2,%3}, [%4];"
                    : "=r"(al[mf][0]), "=r"(al[mf][1]), "=r"(al[mf][2]), "=r"(al[mf][3])
                    : "r"(aLo + off));
            }
            uint32_t bh[NF][2], bl[NF][2];
            #pragma unroll
            for (int nf2 = 0; nf2 < NF / 2; nf2++) {
                int r = wn * (NF * 8) + nf2 * 16 + (lane & 7) + ((lane >> 4) << 3);
                int kzh = it * 64 + kk + ((lane >> 3) & 1) * 8;
                int kzl = kzh + K;
                uint32_t adh = sBu + r * BROW + ((kzh >> 6) << 7) + ((((kzh >> 3) & 7) ^ (r & 7)) << 4);
                uint32_t adl = sBu + r * BROW + ((kzl >> 6) << 7) + ((((kzl >> 3) & 7) ^ (r & 7)) << 4);
                asm volatile("ldmatrix.sync.aligned.m8n8.x4.shared.b16 {%0,%1,%2,%3}, [%4];"
                    : "=r"(bh[2 * nf2][0]), "=r"(bh[2 * nf2][1]),
                      "=r"(bh[2 * nf2 + 1][0]), "=r"(bh[2 * nf2 + 1][1]) : "r"(adh));
                asm volatile("ldmatrix.sync.aligned.m8n8.x4.shared.b16 {%0,%1,%2,%3}, [%4];"
                    : "=r"(bl[2 * nf2][0]), "=r"(bl[2 * nf2][1]),
                      "=r"(bl[2 * nf2 + 1][0]), "=r"(bl[2 * nf2 + 1][1]) : "r"(adl));
            }
            #pragma unroll
            for (int mf = 0; mf < 2; mf++)
                #pragma unroll
                for (int nf = 0; nf < NF; nf++) {
                    MMA3(acc[mf][nf], ah[mf], al[mf], bh[nf], bl[nf]);
                }
        }
        __syncthreads();
    }

    #pragma unroll
    for (int mf = 0; mf < 2; mf++) {
        int r1 = m0 + wm * 32 + mf * 16 + (lane >> 2);
        int r2 = r1 + 8;
        #pragma unroll
        for (int nf = 0; nf < NF; nf++) {
            int col = wn * (NF * 8) + nf * 8 + (lane & 3) * 2;
            float bx = __ldg(bias + col), by = __ldg(bias + col + 1);
            if (r1 < M) {
                float2 v = make_float2(acc[mf][nf][0] + bx, acc[mf][nf][1] + by);
                *(float2*)(Out + (size_t)r1 * N_ + col) = v;
            }
            if (r2 < M) {
                float2 v = make_float2(acc[mf][nf][2] + bx, acc[mf][nf][3] + by);
                *(float2*)(Out + (size_t)r2 * N_ + col) = v;
            }
        }
    }
}

// ---------------------------------------------------------------------------
// Weights-only prep (monolithic, main stream — R8 configuration)
// ---------------------------------------------------------------------------
__global__ void prep_w(const float* __restrict__ w1, const float* __restrict__ wm,
                       const float* __restrict__ w2,
                       __nv_bfloat16* __restrict__ w1c, __nv_bfloat16* __restrict__ wmc,
                       __nv_bfloat16* __restrict__ w2c) {
    int j = blockIdx.x * blockDim.x + threadIdx.x;
    float f;
    __nv_bfloat16* dhi;
    int K;
    if (j < DIN * HH) {
        int k = j / HH, n = j % HH;
        f = w1[j];
        dhi = w1c + (size_t)n * 2 * DIN + k;
        K = DIN;
    } else if (j < DIN * HH + 2 * HH * HH) {
        int q = j - DIN * HH;
        int l = q >> 14; q &= 16383;
        int k = q / HH, n = q % HH;
        f = wm[(size_t)l * HH * HH + q];
        dhi = wmc + (size_t)l * HH * 2 * HH + (size_t)n * 2 * HH + k;
        K = HH;
    } else if (j < DIN * HH + 2 * HH * HH + HH * CC) {
        int q = j - DIN * HH - 2 * HH * HH;
        int k = q / CC, n = q % CC;
        f = w2[q];
        dhi = w2c + (size_t)n * 2 * HH + k;
        K = HH;
    } else return;
    __nv_bfloat16 h = __float2bfloat16(f);
    dhi[0] = h;
    dhi[K] = __float2bfloat16(f - __bfloat162float(h));
}

// ---------------------------------------------------------------------------
// CSR construction
// ---------------------------------------------------------------------------
__global__ void hist_kernel(const int* __restrict__ row, int* __restrict__ cnt, int E) {
    int i = blockIdx.x * blockDim.x + threadIdx.x;
    if (i < E) atomicAdd(&cnt[row[i]], 1);
}
__global__ void scan_kernel(int* __restrict__ cnt, int* __restrict__ rowptr,
                            int* __restrict__ cursor) {
    __shared__ int wsum[32];
    __shared__ int carry_s;
    const int tid = threadIdx.x;
    const int lane = tid & 31;
    const int wid = tid >> 5;
    if (tid == 0) { carry_s = 0; rowptr[0] = 0; }
    __syncthreads();
    for (int base = 0; base < NN; base += 1024) {
        int i = base + tid;
        int v = (i < NN) ? cnt[i] : 0;
        if (i < NN) cnt[i] = 0;
        int incl = v;
        #pragma unroll
        for (int o = 1; o < 32; o <<= 1) {
            int t = __shfl_up_sync(0xFFFFFFFFu, incl, o);
            if (lane >= o) incl += t;
        }
        if (lane == 31) wsum[wid] = incl;
        __syncthreads();
        if (wid == 0) {
            int w = wsum[lane];
            #pragma unroll
            for (int o = 1; o < 32; o <<= 1) {
                int t = __shfl_up_sync(0xFFFFFFFFu, w, o);
                if (lane >= o) w += t;
            }
            wsum[lane] = w;
        }
        __syncthreads();
        int offset = (wid > 0) ? wsum[wid - 1] : 0;
        int total = wsum[31];
        int carry = carry_s;
        incl += offset;
        if (i < NN) {
            rowptr[i + 1] = carry + incl;
            cursor[i]     = carry + incl - v;
        }
        __syncthreads();
        if (tid == 0) carry_s = carry + total;
        __syncthreads();
    }
}
__global__ void scatter_kernel(const int* __restrict__ row, const int* __restrict__ col,
                               const float* __restrict__ val, int* __restrict__ cursor,
                               int2* __restrict__ cpack, int E) {
    int i = blockIdx.x * blockDim.x + threadIdx.x;
    if (i >= E) return;
    int pos = atomicAdd(&cursor[row[i]], 1);
    cpack[pos] = make_int2(col[i], __float_as_int(val[i]));
}

// ---------------------------------------------------------------------------
// CSR SPMM: one warp per row, 4-deep gather pipeline, fused epilogue + bf16
// [hi|lo] split (uint2 stores).
// ---------------------------------------------------------------------------
template<int D, int MODE>
__global__ void spmm_csr(const int* __restrict__ rowptr, const int2* __restrict__ cpack,
                         const float* __restrict__ mat, float* __restrict__ dst,
                         const float* __restrict__ ts, __nv_bfloat16* __restrict__ acat) {
    int r = blockIdx.x * (blockDim.x >> 5) + (threadIdx.x >> 5);
    if (r >= NN) return;
    int lane = threadIdx.x & 31;
    int s = __ldg(&rowptr[r]);
    int e = __ldg(&rowptr[r + 1]);

    if (D == 128) {
        float4 acc = make_float4(0.f, 0.f, 0.f, 0.f);
        int i = s;
        for (; i + 4 <= e; i += 4) {
            int2 p0 = __ldg(&cpack[i]);
            int2 p1 = __ldg(&cpack[i + 1]);
            int2 p2 = __ldg(&cpack[i + 2]);
            int2 p3 = __ldg(&cpack[i + 3]);
            float4 m0 = __ldg((const float4*)(mat + (size_t)p0.x * 128) + lane);
            float4 m1 = __ldg((const float4*)(mat + (size_t)p1.x * 128) + lane);
            float4 m2 = __ldg((const float4*)(mat + (size_t)p2.x * 128) + lane);
            float4 m3 = __ldg((const float4*)(mat + (size_t)p3.x * 128) + lane);
            float v0 = __int_as_float(p0.y), v1 = __int_as_float(p1.y);
            float v2 = __int_as_float(p2.y), v3 = __int_as_float(p3.y);
            acc.x = fmaf(v0, m0.x, acc.x); acc.y = fmaf(v0, m0.y, acc.y);
            acc.z = fmaf(v0, m0.z, acc.z); acc.w = fmaf(v0, m0.w, acc.w);
            acc.x = fmaf(v1, m1.x, acc.x); acc.y = fmaf(v1, m1.y, acc.y);
            acc.z = fmaf(v1, m1.z, acc.z); acc.w = fmaf(v1, m1.w, acc.w);
            acc.x = fmaf(v2, m2.x, acc.x); acc.y = fmaf(v2, m2.y, acc.y);
            acc.z = fmaf(v2, m2.z, acc.z); acc.w = fmaf(v2, m2.w, acc.w);
            acc.x = fmaf(v3, m3.x, acc.x); acc.y = fmaf(v3, m3.y, acc.y);
            acc.z = fmaf(v3, m3.z, acc.z); acc.w = fmaf(v3, m3.w, acc.w);
        }
        for (; i < e; i++) {
            int2 p = __ldg(&cpack[i]);
            float v = __int_as_float(p.y);
            float4 m = __ldg((const float4*)(mat + (size_t)p.x * 128) + lane);
            acc.x = fmaf(v, m.x, acc.x); acc.y = fmaf(v, m.y, acc.y);
            acc.z = fmaf(v, m.z, acc.z); acc.w = fmaf(v, m.w, acc.w);
        }
        float4* o = (float4*)(dst + (size_t)r * 128) + lane;
        float4 hv;
        if (MODE == 0) {
            hv.x = fmaxf(acc.x, 0.f); hv.y = fmaxf(acc.y, 0.f);
            hv.z = fmaxf(acc.z, 0.f); hv.w = fmaxf(acc.w, 0.f);
        } else {
            float dt = *ts;
            hv = *o;
            hv.x = fmaf(fmaxf(acc.x, 0.f), dt, hv.x);
            hv.y = fmaf(fmaxf(acc.y, 0.f), dt, hv.y);
            hv.z = fmaf(fmaxf(acc.z, 0.f), dt, hv.z);
            hv.w = fmaf(fmaxf(acc.w, 0.f), dt, hv.w);
        }
        *o = hv;
        __nv_bfloat162 hl[2], ll[2];
        hl[0] = bhi2(hv.x, hv.y); hl[1] = bhi2(hv.z, hv.w);
        ll[0] = blo2(hv.x, hv.y, hl[0]); ll[1] = blo2(hv.z, hv.w, hl[1]);
        __nv_bfloat16* row = acat + (size_t)r * 256;
        *(uint2*)(row + lane * 4)       = *(const uint2*)hl;
        *(uint2*)(row + 128 + lane * 4) = *(const uint2*)ll;
    } else {
        float2 acc = make_float2(0.f, 0.f);
        int i = s;
        for (; i + 4 <= e; i += 4) {
            int2 p0 = __ldg(&cpack[i]);
            int2 p1 = __ldg(&cpack[i + 1]);
            int2 p2 = __ldg(&cpack[i + 2]);
            int2 p3 = __ldg(&cpack[i + 3]);
            float2 m0 = __ldg((const float2*)(mat + (size_t)p0.x * 64) + lane);
            float2 m1 = __ldg((const float2*)(mat + (size_t)p1.x * 64) + lane);
            float2 m2 = __ldg((const float2*)(mat + (size_t)p2.x * 64) + lane);
            float2 m3 = __ldg((const float2*)(mat + (size_t)p3.x * 64) + lane);
            acc.x = fmaf(__int_as_float(p0.y), m0.x, acc.x);
            acc.y = fmaf(__int_as_float(p0.y), m0.y, acc.y);
            acc.x = fmaf(__int_as_float(p1.y), m1.x, acc.x);
            acc.y = fmaf(__int_as_float(p1.y), m1.y, acc.y);
            acc.x = fmaf(__int_as_float(p2.y), m2.x, acc.x);
            acc.y = fmaf(__int_as_float(p2.y), m2.y, acc.y);
            acc.x = fmaf(__int_as_float(p3.y), m3.x, acc.x);
            acc.y = fmaf(__int_as_float(p3.y), m3.y, acc.y);
        }
        for (; i < e; i++) {
            int2 p = __ldg(&cpack[i]);
            float v = __int_as_float(p.y);
            float2 m = __ldg((const float2*)(mat + (size_t)p.x * 64) + lane);
            acc.x = fmaf(v, m.x, acc.x);
            acc.y = fmaf(v, m.y, acc.y);
        }
        *((float2*)(dst + (size_t)r * 64) + lane) = acc;
    }
}

// ---------------------------------------------------------------------------
// Launch sequence (exact R8 topology)
// ---------------------------------------------------------------------------
extern "C" void kernel_launch(void* const* d_in, const int* in_sizes, int n_in,
                              void* d_out, int out_size) {
    const float* x    = (const float*)d_in[0];
    const int*   erow = (const int*)  d_in[1];
    const int*   ecol = (const int*)  d_in[2];
    const float* eval = (const float*)d_in[3];
    const float* w1   = (const float*)d_in[4];
    const float* b1   = (const float*)d_in[5];
    const float* wm   = (const float*)d_in[6];
    const float* bm   = (const float*)d_in[7];
    const float* w2   = (const float*)d_in[8];
    const float* b2   = (const float*)d_in[9];
    const float* ts   = (const float*)d_in[10];
    float* out = (float*)d_out;

    float *y, *h;
    int *cnt, *rowptr, *cursor;
    int2* cpack;
    __nv_bfloat16 *acat, *w1c, *wmc, *w2c;
    cudaGetSymbolAddress((void**)&y,      g_y);
    cudaGetSymbolAddress((void**)&h,      g_h);
    cudaGetSymbolAddress((void**)&cnt,    g_cnt);
    cudaGetSymbolAddress((void**)&rowptr, g_rowptr);
    cudaGetSymbolAddress((void**)&cursor, g_cursor);
    cudaGetSymbolAddress((void**)&cpack,  g_cpack);
    cudaGetSymbolAddress((void**)&acat,   g_acat);
    cudaGetSymbolAddress((void**)&w1c,    g_w1c);
    cudaGetSymbolAddress((void**)&wmc,    g_wmc);
    cudaGetSymbolAddress((void**)&w2c,    g_w2c);

    const int SMX = 128 * (4 * DIN) + 2 * 128 * 128;  // 163840
    const int SM2 = 128 * (4 * HH)  + 4 * 128 * 128;  // 131072
    const int SM4 = 64  * (4 * HH)  + 4 * 128 * 128;  // 98304
    cudaFuncSetAttribute((const void*)&gemm_mma_x,
                         cudaFuncAttributeMaxDynamicSharedMemorySize, SMX);
    cudaFuncSetAttribute((const void*)&gemm_mma<128, HH>,
                         cudaFuncAttributeMaxDynamicSharedMemorySize, SM2);
    cudaFuncSetAttribute((const void*)&gemm_mma<64, HH>,
                         cudaFuncAttributeMaxDynamicSharedMemorySize, SM4);
    cudaGetLastError();

    const int gemm_blocks = (NN + 127) / 128;   // 313
    const int spmm_blocks = (NN + 7) / 8;       // 5000
    const int e_blocks = (EE + 255) / 256;
    const int w_total = DIN * HH + 2 * HH * HH + HH * CC;

    const bool fork = (g_side != nullptr) && (g_ev0 != nullptr) && (g_ev1 != nullptr);

    if (fork) {
        cudaEventRecord(g_ev0, 0);
        cudaStreamWaitEvent(g_side, g_ev0, 0);
        hist_kernel<<<e_blocks, 256, 0, g_side>>>(erow, cnt, EE);
        scan_kernel<<<1, 1024, 0, g_side>>>(cnt, rowptr, cursor);
        scatter_kernel<<<e_blocks, 256, 0, g_side>>>(erow, ecol, eval, cursor, cpack, EE);
        cudaEventRecord(g_ev1, g_side);
    }

    // Main stream: weights split, then stage-1 GEMM (x converted in-kernel)
    prep_w<<<(w_total + 255) / 256, 256>>>(w1, wm, w2, w1c, wmc, w2c);
    gemm_mma_x<<<gemm_blocks, 256, SMX>>>(x, w1c, b1, y, NN);

    if (fork) {
        cudaStreamWaitEvent(0, g_ev1, 0);
    } else {
        hist_kernel<<<e_blocks, 256>>>(erow, cnt, EE);
        scan_kernel<<<1, 1024>>>(cnt, rowptr, cursor);
        scatter_kernel<<<e_blocks, 256>>>(erow, ecol, eval, cursor, cpack, EE);
    }

    // Stage 1: h = relu(A @ (x W1 + b1))
    spmm_csr<128, 0><<<spmm_blocks, 256>>>(rowptr, cpack, y, h, ts, acat);

    // Stage 2,3: h += relu(A @ (h Wm + bm)) * dt
    for (int i = 0; i < 2; i++) {
        gemm_mma<128, HH><<<gemm_blocks, 256, SM2>>>(
            acat, wmc + (size_t)i * HH * 2 * HH, bm + (size_t)i * HH, y, NN);
        spmm_csr<128, 1><<<spmm_blocks, 256>>>(rowptr, cpack, y, h, ts, acat);
    }

    // Stage 4: out = A @ (h W2 + b2)
    gemm_mma<64, HH><<<gemm_blocks, 256, SM4>>>(acat, w2c, b2, y, NN);
    spmm_csr<64, 2><<<spmm_blocks, 256>>>(rowptr, cpack, y, out, ts, nullptr);
}